// round 10
// baseline (speedup 1.0000x reference)
#include <cuda_runtime.h>
#include <cuda_fp16.h>
#include <cstdint>

// ---------------- problem constants ----------------
#define HDIM   256
#define WDIM   256
#define HW     16384          // 128*128 output pixels
#define KB     1024           // K (channels)
#define COUT   512
#define NGROUP 128
#define GSIZE  8
#define GN_EPS 1e-5f
#define TITER  32             // 1024 / 32

// ---------------- device scratch ----------------
__device__ __half g_B[(size_t)KB * HW];        // 32 MB: Y fp16, [k][n]
__device__ __half g_A[(size_t)COUT * KB];      // 1 MB: folded W fp16, [o][k]
__device__ float g_psum[4 * KB];               // per-chunk partial sums
__device__ float g_psumsq[4 * KB];
__device__ float g_biaso[COUT];

// ---------------- PTX helpers (target-generic only) ----------------
__device__ __forceinline__ uint32_t s2u(const void* p) {
    uint32_t a;
    asm("{ .reg .u64 t; cvta.to.shared.u64 t, %1; cvt.u32.u64 %0, t; }" : "=r"(a) : "l"(p));
    return a;
}
__device__ __forceinline__ void cp16(uint32_t dst, const void* src) {
    asm volatile("cp.async.cg.shared.global [%0], [%1], 16;" :: "r"(dst), "l"(src));
}
__device__ __forceinline__ void cp_commit() {
    asm volatile("cp.async.commit_group;" ::: "memory");
}
__device__ __forceinline__ void cp_wait2() {
    asm volatile("cp.async.wait_group 2;" ::: "memory");
}
__device__ __forceinline__ void ldsm4(uint32_t* r, uint32_t a) {
    asm volatile("ldmatrix.sync.aligned.m8n8.x4.shared.b16 {%0,%1,%2,%3}, [%4];"
                 : "=r"(r[0]), "=r"(r[1]), "=r"(r[2]), "=r"(r[3]) : "r"(a));
}
__device__ __forceinline__ void ldsm4t(uint32_t* r, uint32_t a) {
    asm volatile("ldmatrix.sync.aligned.m8n8.x4.trans.shared.b16 {%0,%1,%2,%3}, [%4];"
                 : "=r"(r[0]), "=r"(r[1]), "=r"(r[2]), "=r"(r[3]) : "r"(a));
}
__device__ __forceinline__ void mma16816(float* d, const uint32_t* a, uint32_t b0, uint32_t b1) {
    asm volatile(
        "mma.sync.aligned.m16n8k16.row.col.f32.f16.f16.f32 "
        "{%0,%1,%2,%3}, {%4,%5,%6,%7}, {%8,%9}, {%0,%1,%2,%3};"
        : "+f"(d[0]), "+f"(d[1]), "+f"(d[2]), "+f"(d[3])
        : "r"(a[0]), "r"(a[1]), "r"(a[2]), "r"(a[3]), "r"(b0), "r"(b1));
}

// ---------------- Kernel A: Haar bands -> fp16 + partial stats (R5-best) ------
__global__ __launch_bounds__(256) void haar_kernel(const float* __restrict__ x) {
    const int cx    = blockIdx.x;            // input channel 0..255
    const int chunk = blockIdx.y;            // 0..3
    const float* xp = x + (size_t)cx * (HDIM * WDIM);

    float s0=0.f,s1=0.f,s2=0.f,s3=0.f,q0=0.f,q1=0.f,q2=0.f,q3=0.f;

    const int i2_lo = chunk * 4096;
    const int i2_hi = i2_lo + 4096;
    for (int i2 = i2_lo + threadIdx.x * 2; i2 < i2_hi; i2 += 512) {
        const int h = i2 >> 7;
        const int w = i2 & 127;               // even
        const float4 r0 = *(const float4*)(xp + (size_t)(2*h)   * WDIM + 2*w);
        const float4 r1 = *(const float4*)(xp + (size_t)(2*h+1) * WDIM + 2*w);
        float v0[4], v1[4];
        v0[0] = 0.5f*( r0.x + r0.y + r1.x + r1.y);
        v0[1] = 0.5f*(-r0.x - r0.y + r1.x + r1.y);
        v0[2] = 0.5f*(-r0.x + r0.y - r1.x + r1.y);
        v0[3] = 0.5f*( r0.x - r0.y - r1.x + r1.y);
        v1[0] = 0.5f*( r0.z + r0.w + r1.z + r1.w);
        v1[1] = 0.5f*(-r0.z - r0.w + r1.z + r1.w);
        v1[2] = 0.5f*(-r0.z + r0.w - r1.z + r1.w);
        v1[3] = 0.5f*( r0.z - r0.w - r1.z + r1.w);
        s0 += v0[0]+v1[0]; q0 += v0[0]*v0[0] + v1[0]*v1[0];
        s1 += v0[1]+v1[1]; q1 += v0[1]*v0[1] + v1[1]*v1[1];
        s2 += v0[2]+v1[2]; q2 += v0[2]*v0[2] + v1[2]*v1[2];
        s3 += v0[3]+v1[3]; q3 += v0[3]*v0[3] + v1[3]*v1[3];
        #pragma unroll
        for (int b = 0; b < 4; b++) {
            const size_t c = (size_t)b * 256 + cx;
            *(__half2*)&g_B[c * HW + i2] =
                __halves2half2(__float2half_rn(v0[b]), __float2half_rn(v1[b]));
        }
    }

    __shared__ float red[256];
    float vals[8] = {s0,s1,s2,s3,q0,q1,q2,q3};
    for (int q = 0; q < 8; q++) {
        red[threadIdx.x] = vals[q];
        __syncthreads();
        for (int off = 128; off > 0; off >>= 1) {
            if (threadIdx.x < off) red[threadIdx.x] += red[threadIdx.x + off];
            __syncthreads();
        }
        if (threadIdx.x == 0) {
            const int band = q & 3;
            const int idx = chunk * KB + band * 256 + cx;
            if (q < 4) g_psum[idx]   = red[0];
            else       g_psumsq[idx] = red[0];
        }
        __syncthreads();
    }
}

// ---------------- Kernel B: stats + fold affine into fp16 weights ------
__global__ __launch_bounds__(256) void foldw_kernel(const float* __restrict__ w,
                                                    const float* __restrict__ scale,
                                                    const float* __restrict__ bias) {
    __shared__ float sa[KB], sb[KB];
    const int tid = threadIdx.x;
    if (tid < NGROUP) {
        const int g = tid;
        float s = 0.f, q = 0.f;
        #pragma unroll
        for (int j = 0; j < GSIZE; j++) {
            const int c = g*GSIZE + j;
            #pragma unroll
            for (int ch = 0; ch < 4; ch++) {
                s += g_psum[ch * KB + c];
                q += g_psumsq[ch * KB + c];
            }
        }
        const float inv  = 1.0f / (float)(GSIZE * HW);
        const float mean = s * inv;
        const float var  = q * inv - mean * mean;
        const float rstd = rsqrtf(var + GN_EPS);
        #pragma unroll
        for (int j = 0; j < GSIZE; j++) {
            const int c = g*GSIZE + j;
            const float a = scale[c] * rstd;
            sa[c] = a;
            sb[c] = bias[c] - mean * a;
        }
    }
    __syncthreads();

    const int o = blockIdx.x;                // 0..511
    float part = 0.f;
    for (int c = tid; c < KB; c += 256) {
        const float wv = w[(size_t)o * KB + c];
        g_A[(size_t)o * KB + c] = __float2half_rn(wv * sa[c]);
        part += wv * sb[c];
    }
    __shared__ float red[256];
    red[tid] = part;
    __syncthreads();
    for (int off = 128; off > 0; off >>= 1) {
        if (tid < off) red[tid] += red[tid + off];
        __syncthreads();
    }
    if (tid == 0) g_biaso[o] = red[0];
}

// ---------------- Kernel C: mma.sync fp16 GEMM + bias + ReLU ----
// C[512,16384] = W[512,1024] @ Y[1024,16384]
// CTA tile 128(M) x 64(N), BK=32; 8 warps, warp tile 32x32 (4x2 warp grid).
// Stage: A 8KB + B 4KB = 12KB; 4 stages = 48KB. 4 CTAs/SM (32 warps).
#define STAGE_BYTES 12288
#define GEMM_SMEM   (4 * STAGE_BYTES)

__device__ __forceinline__ void load_stage(int tid, int j, uint32_t sbase, int m0, int n0) {
    const uint32_t st = sbase + (uint32_t)(j & 3) * STAGE_BYTES;
    const int koff = j << 5;                 // 0..992
    const __half* Ab = g_A + (size_t)m0 * KB + koff;
    const __half* Bb = g_B + (size_t)koff * HW + n0;
    // A: 128 rows(m) x 4 chunks(kc of 8 halves); unit = m*4 + (kc ^ ((m>>1)&3))
    #pragma unroll
    for (int t = 0; t < 2; t++) {
        const int u = tid + t * 256;
        const int m = u >> 2, kc = u & 3;
        const uint32_t du = (uint32_t)(m * 4 + (kc ^ ((m >> 1) & 3))) * 16;
        cp16(st + du, Ab + (size_t)m * KB + kc * 8);
    }
    // B: 32 rows(k) x 8 chunks(nc of 8 halves); unit = k*8 + (nc ^ (k&7))
    {
        const int k = tid >> 3, nc = tid & 7;
        const uint32_t du = (uint32_t)(k * 8 + (nc ^ (k & 7)));
        cp16(st + 8192 + du * 16, Bb + (size_t)k * HW + nc * 8);
    }
}

__global__ __launch_bounds__(256, 4) void gemm_mma_kernel(float* __restrict__ out) {
    extern __shared__ char smem[];
    const uint32_t sbase = s2u(smem);
    const int tid  = threadIdx.x;
    const int wid  = tid >> 5;
    const int lane = tid & 31;
    const int n0 = blockIdx.x * 64;
    const int m0 = blockIdx.y * 128;
    const int wm = wid >> 1;                 // 0..3
    const int wn = wid & 1;                  // 0..1
    const int mbase = wm * 32;
    const int nbase = wn * 32;

    const int r15 = lane & 15;
    const int hi  = lane >> 4;
    const int sA  = (r15 >> 1) & 3;          // A swizzle term
    const int s7  = r15 & 7;                 // B swizzle term

    float acc[2][4][4];
    #pragma unroll
    for (int i = 0; i < 2; i++)
        #pragma unroll
        for (int j = 0; j < 4; j++)
            #pragma unroll
            for (int q = 0; q < 4; q++) acc[i][j][q] = 0.f;

    load_stage(tid, 0, sbase, m0, n0); cp_commit();
    load_stage(tid, 1, sbase, m0, n0); cp_commit();
    load_stage(tid, 2, sbase, m0, n0); cp_commit();

    for (int j = 0; j < TITER; j++) {
        cp_wait2();
        __syncthreads();
        if (j + 3 < TITER) load_stage(tid, j + 3, sbase, m0, n0);
        cp_commit();

        const uint32_t st = sbase + (uint32_t)(j & 3) * STAGE_BYTES;
        #pragma unroll
        for (int kk = 0; kk < 2; kk++) {
            // B frags: warp covers n = nbase..nbase+31 -> 2 ldsm4t
            uint32_t b[2][4];
            #pragma unroll
            for (int p = 0; p < 2; p++) {
                const int k   = kk * 16 + r15;
                const int ncg = wn * 4 + p * 2 + hi;
                ldsm4t(b[p], st + 8192 + (uint32_t)((k * 8 + (ncg ^ s7)) * 16));
            }
            // A frags: warp covers m = mbase..mbase+31 -> 2 ldsm4
            uint32_t a[2][4];
            #pragma unroll
            for (int mf = 0; mf < 2; mf++) {
                const int row = mbase + mf * 16 + r15;
                ldsm4(a[mf], st + (uint32_t)((row * 4 + ((kk * 2 + hi) ^ sA)) * 16));
            }
            #pragma unroll
            for (int mf = 0; mf < 2; mf++)
                #pragma unroll
                for (int nf = 0; nf < 4; nf++)
                    mma16816(acc[mf][nf], a[mf], b[nf >> 1][(nf & 1) * 2],
                             b[nf >> 1][(nf & 1) * 2 + 1]);
        }
    }

    // epilogue: bias + ReLU + float2 stores
    const int qrow = lane >> 2;
    const int qcol = (lane & 3) * 2;
    #pragma unroll
    for (int mf = 0; mf < 2; mf++) {
        const int row0 = m0 + mbase + mf * 16 + qrow;
        const float bi0 = g_biaso[row0];
        const float bi1 = g_biaso[row0 + 8];
        float* o0 = out + (size_t)row0 * HW + n0 + nbase + qcol;
        float* o1 = out + (size_t)(row0 + 8) * HW + n0 + nbase + qcol;
        #pragma unroll
        for (int nf = 0; nf < 4; nf++) {
            float2 v0, v1;
            v0.x = fmaxf(acc[mf][nf][0] + bi0, 0.f);
            v0.y = fmaxf(acc[mf][nf][1] + bi0, 0.f);
            v1.x = fmaxf(acc[mf][nf][2] + bi1, 0.f);
            v1.y = fmaxf(acc[mf][nf][3] + bi1, 0.f);
            *(float2*)(o0 + nf * 8) = v0;
            *(float2*)(o1 + nf * 8) = v1;
        }
    }
}

// ---------------- launch ----------------
extern "C" void kernel_launch(void* const* d_in, const int* in_sizes, int n_in,
                              void* d_out, int out_size) {
    const float* x        = (const float*)d_in[0];
    const float* gn_scale = (const float*)d_in[1];
    const float* gn_bias  = (const float*)d_in[2];
    const float* w_proj   = (const float*)d_in[3];
    float* out = (float*)d_out;

    cudaFuncSetAttribute(gemm_mma_kernel,
                         cudaFuncAttributeMaxDynamicSharedMemorySize, GEMM_SMEM);

    dim3 hgrid(256, 4);
    haar_kernel<<<hgrid, 256>>>(x);
    foldw_kernel<<<COUT, 256>>>(w_proj, gn_scale, gn_bias);
    dim3 grid(HW / 64, COUT / 128);
    gemm_mma_kernel<<<grid, 256, GEMM_SMEM>>>(out);
}

// round 11
// speedup vs baseline: 1.0554x; 1.0554x over previous
#include <cuda_runtime.h>
#include <cuda_fp16.h>
#include <cstdint>

// ---------------- problem constants ----------------
#define HDIM   256
#define WDIM   256
#define HW     16384          // 128*128 output pixels
#define KB     1024           // K (channels)
#define COUT   512
#define NGROUP 128
#define GSIZE  8
#define GN_EPS 1e-5f
#define TITER  16             // 1024 / 64

// ---------------- device scratch ----------------
__device__ __half g_B[(size_t)KB * HW];        // 32 MB: Y fp16, [k][n]
__device__ __half g_A[(size_t)COUT * KB];      // 1 MB: folded W fp16, [o][k]
__device__ float g_psum[2 * KB];               // per-chunk partial sums
__device__ float g_psumsq[2 * KB];
__device__ float g_biaso[COUT];

// ---------------- PTX helpers (target-generic only) ----------------
__device__ __forceinline__ uint32_t s2u(const void* p) {
    uint32_t a;
    asm("{ .reg .u64 t; cvta.to.shared.u64 t, %1; cvt.u32.u64 %0, t; }" : "=r"(a) : "l"(p));
    return a;
}
__device__ __forceinline__ void cp16(uint32_t dst, const void* src) {
    asm volatile("cp.async.cg.shared.global [%0], [%1], 16;" :: "r"(dst), "l"(src));
}
__device__ __forceinline__ void cp_commit() {
    asm volatile("cp.async.commit_group;" ::: "memory");
}
__device__ __forceinline__ void cp_wait1() {
    asm volatile("cp.async.wait_group 1;" ::: "memory");
}
__device__ __forceinline__ void ldsm4(uint32_t* r, uint32_t a) {
    asm volatile("ldmatrix.sync.aligned.m8n8.x4.shared.b16 {%0,%1,%2,%3}, [%4];"
                 : "=r"(r[0]), "=r"(r[1]), "=r"(r[2]), "=r"(r[3]) : "r"(a));
}
__device__ __forceinline__ void ldsm4t(uint32_t* r, uint32_t a) {
    asm volatile("ldmatrix.sync.aligned.m8n8.x4.trans.shared.b16 {%0,%1,%2,%3}, [%4];"
                 : "=r"(r[0]), "=r"(r[1]), "=r"(r[2]), "=r"(r[3]) : "r"(a));
}
__device__ __forceinline__ void mma16816(float* d, const uint32_t* a, uint32_t b0, uint32_t b1) {
    asm volatile(
        "mma.sync.aligned.m16n8k16.row.col.f32.f16.f16.f32 "
        "{%0,%1,%2,%3}, {%4,%5,%6,%7}, {%8,%9}, {%0,%1,%2,%3};"
        : "+f"(d[0]), "+f"(d[1]), "+f"(d[2]), "+f"(d[3])
        : "r"(a[0]), "r"(a[1]), "r"(a[2]), "r"(a[3]), "r"(b0), "r"(b1));
}

// ---------------- Kernel A: Haar bands -> fp16 + partial stats ----------------
// grid (256 channels, 2 half-planes); block: 64 output rows = 8192 pixels.
// Each thread per iteration: 2 pixel-pairs from disjoint quadrants (MLP=4 loads).
__global__ __launch_bounds__(256) void haar_kernel(const float* __restrict__ x) {
    const int cx    = blockIdx.x;            // input channel 0..255
    const int chunk = blockIdx.y;            // 0..1
    const float* xp = x + (size_t)cx * (HDIM * WDIM);

    float s0=0.f,s1=0.f,s2=0.f,s3=0.f,q0=0.f,q1=0.f,q2=0.f,q3=0.f;

    const int base = chunk * 8192;
    for (int t = threadIdx.x * 2; t < 4096; t += 512) {
        const int iA = base + t;             // quadrant A
        const int iB = iA + 4096;            // quadrant B
        const int hA = iA >> 7, wA = iA & 127;
        const int hB = iB >> 7, wB = iB & 127;
        // 4 independent loads up front
        const float4 a0 = *(const float4*)(xp + (size_t)(2*hA)   * WDIM + 2*wA);
        const float4 a1 = *(const float4*)(xp + (size_t)(2*hA+1) * WDIM + 2*wA);
        const float4 b0 = *(const float4*)(xp + (size_t)(2*hB)   * WDIM + 2*wB);
        const float4 b1 = *(const float4*)(xp + (size_t)(2*hB+1) * WDIM + 2*wB);

        float vA0[4], vA1[4], vB0[4], vB1[4];
        vA0[0] = 0.5f*( a0.x + a0.y + a1.x + a1.y);
        vA0[1] = 0.5f*(-a0.x - a0.y + a1.x + a1.y);
        vA0[2] = 0.5f*(-a0.x + a0.y - a1.x + a1.y);
        vA0[3] = 0.5f*( a0.x - a0.y - a1.x + a1.y);
        vA1[0] = 0.5f*( a0.z + a0.w + a1.z + a1.w);
        vA1[1] = 0.5f*(-a0.z - a0.w + a1.z + a1.w);
        vA1[2] = 0.5f*(-a0.z + a0.w - a1.z + a1.w);
        vA1[3] = 0.5f*( a0.z - a0.w - a1.z + a1.w);
        vB0[0] = 0.5f*( b0.x + b0.y + b1.x + b1.y);
        vB0[1] = 0.5f*(-b0.x - b0.y + b1.x + b1.y);
        vB0[2] = 0.5f*(-b0.x + b0.y - b1.x + b1.y);
        vB0[3] = 0.5f*( b0.x - b0.y - b1.x + b1.y);
        vB1[0] = 0.5f*( b0.z + b0.w + b1.z + b1.w);
        vB1[1] = 0.5f*(-b0.z - b0.w + b1.z + b1.w);
        vB1[2] = 0.5f*(-b0.z + b0.w - b1.z + b1.w);
        vB1[3] = 0.5f*( b0.z - b0.w - b1.z + b1.w);

        #pragma unroll
        for (int b = 0; b < 4; b++) {
            const size_t c = (size_t)b * 256 + cx;
            *(__half2*)&g_B[c * HW + iA] =
                __halves2half2(__float2half_rn(vA0[b]), __float2half_rn(vA1[b]));
            *(__half2*)&g_B[c * HW + iB] =
                __halves2half2(__float2half_rn(vB0[b]), __float2half_rn(vB1[b]));
        }
        s0 += vA0[0]+vA1[0]+vB0[0]+vB1[0];
        q0 += vA0[0]*vA0[0]+vA1[0]*vA1[0]+vB0[0]*vB0[0]+vB1[0]*vB1[0];
        s1 += vA0[1]+vA1[1]+vB0[1]+vB1[1];
        q1 += vA0[1]*vA0[1]+vA1[1]*vA1[1]+vB0[1]*vB0[1]+vB1[1]*vB1[1];
        s2 += vA0[2]+vA1[2]+vB0[2]+vB1[2];
        q2 += vA0[2]*vA0[2]+vA1[2]*vA1[2]+vB0[2]*vB0[2]+vB1[2]*vB1[2];
        s3 += vA0[3]+vA1[3]+vB0[3]+vB1[3];
        q3 += vA0[3]*vA0[3]+vA1[3]*vA1[3]+vB0[3]*vB0[3]+vB1[3]*vB1[3];
    }

    // warp shuffle reduce 8 values, then one smem stage
    float vals[8] = {s0,s1,s2,s3,q0,q1,q2,q3};
    #pragma unroll
    for (int q = 0; q < 8; q++) {
        #pragma unroll
        for (int off = 16; off > 0; off >>= 1)
            vals[q] += __shfl_xor_sync(0xFFFFFFFFu, vals[q], off);
    }
    __shared__ float wred[8][8];             // [warp][metric]
    const int wid = threadIdx.x >> 5;
    const int lid = threadIdx.x & 31;
    if (lid == 0) {
        #pragma unroll
        for (int q = 0; q < 8; q++) wred[wid][q] = vals[q];
    }
    __syncthreads();
    if (threadIdx.x < 8) {
        const int q = threadIdx.x;
        float r = 0.f;
        #pragma unroll
        for (int w = 0; w < 8; w++) r += wred[w][q];
        const int band = q & 3;
        const int idx = chunk * KB + band * 256 + cx;
        if (q < 4) g_psum[idx]   = r;
        else       g_psumsq[idx] = r;
    }
}

// ---------------- Kernel B: stats + fold affine into fp16 weights ------
__global__ __launch_bounds__(256) void foldw_kernel(const float* __restrict__ w,
                                                    const float* __restrict__ scale,
                                                    const float* __restrict__ bias) {
    __shared__ float sa[KB], sb[KB];
    const int tid = threadIdx.x;
    if (tid < NGROUP) {
        const int g = tid;
        float s = 0.f, q = 0.f;
        #pragma unroll
        for (int j = 0; j < GSIZE; j++) {
            const int c = g*GSIZE + j;
            #pragma unroll
            for (int ch = 0; ch < 2; ch++) {
                s += g_psum[ch * KB + c];
                q += g_psumsq[ch * KB + c];
            }
        }
        const float inv  = 1.0f / (float)(GSIZE * HW);
        const float mean = s * inv;
        const float var  = q * inv - mean * mean;
        const float rstd = rsqrtf(var + GN_EPS);
        #pragma unroll
        for (int j = 0; j < GSIZE; j++) {
            const int c = g*GSIZE + j;
            const float a = scale[c] * rstd;
            sa[c] = a;
            sb[c] = bias[c] - mean * a;
        }
    }
    __syncthreads();

    const int o = blockIdx.x;                // 0..511
    float part = 0.f;
    for (int c = tid; c < KB; c += 256) {
        const float wv = w[(size_t)o * KB + c];
        g_A[(size_t)o * KB + c] = __float2half_rn(wv * sa[c]);
        part += wv * sb[c];
    }
    __shared__ float red[256];
    red[tid] = part;
    __syncthreads();
    for (int off = 128; off > 0; off >>= 1) {
        if (tid < off) red[tid] += red[tid + off];
        __syncthreads();
    }
    if (tid == 0) g_biaso[o] = red[0];
}

// ---------------- Kernel C: mma.sync fp16 GEMM + bias + ReLU (R9-best) ----
// CTA tile 128(M) x 64(N), BK=64; 8 warps, warp tile 32x32 (4x2 warp grid).
// Stage: A 16KB + B 8KB = 24KB; 3 stages = 72KB. 3 CTAs/SM (24 warps).
#define STAGE_BYTES 24576
#define GEMM_SMEM   (3 * STAGE_BYTES)

__device__ __forceinline__ void load_stage(int tid, int j, uint32_t sbase, int m0, int n0) {
    const uint32_t st = sbase + (uint32_t)(j % 3) * STAGE_BYTES;
    const int koff = j << 6;                 // 0..960
    const __half* Ab = g_A + (size_t)m0 * KB + koff;
    const __half* Bb = g_B + (size_t)koff * HW + n0;
    // A: 128 rows(m) x 8 chunks(kc of 8 halves); unit = m*8 + (kc ^ (m&7))
    #pragma unroll
    for (int t = 0; t < 4; t++) {
        const int u = tid + t * 256;
        const int m = u >> 3, kc = u & 7;
        const uint32_t du = (uint32_t)(m * 8 + (kc ^ (m & 7))) * 16;
        cp16(st + du, Ab + (size_t)m * KB + kc * 8);
    }
    // B: 64 rows(k) x 8 chunks(nc of 8 halves); unit = k*8 + (nc ^ (k&7))
    #pragma unroll
    for (int t = 0; t < 2; t++) {
        const int u = tid + t * 256;
        const int k = u >> 3, nc = u & 7;
        const uint32_t du = (uint32_t)(k * 8 + (nc ^ (k & 7)));
        cp16(st + 16384 + du * 16, Bb + (size_t)k * HW + nc * 8);
    }
}

__global__ __launch_bounds__(256, 3) void gemm_mma_kernel(float* __restrict__ out) {
    extern __shared__ char smem[];
    const uint32_t sbase = s2u(smem);
    const int tid  = threadIdx.x;
    const int wid  = tid >> 5;
    const int lane = tid & 31;
    const int n0 = blockIdx.x * 64;
    const int m0 = blockIdx.y * 128;
    const int wm = wid >> 1;                 // 0..3
    const int wn = wid & 1;                  // 0..1
    const int mbase = wm * 32;
    const int nbase = wn * 32;

    const int r15 = lane & 15;
    const int hi  = lane >> 4;
    const int s7  = r15 & 7;

    float acc[2][4][4];
    #pragma unroll
    for (int i = 0; i < 2; i++)
        #pragma unroll
        for (int j = 0; j < 4; j++)
            #pragma unroll
            for (int q = 0; q < 4; q++) acc[i][j][q] = 0.f;

    load_stage(tid, 0, sbase, m0, n0); cp_commit();
    load_stage(tid, 1, sbase, m0, n0); cp_commit();

    for (int j = 0; j < TITER; j++) {
        cp_wait1();
        __syncthreads();
        if (j + 2 < TITER) load_stage(tid, j + 2, sbase, m0, n0);
        cp_commit();

        const uint32_t st = sbase + (uint32_t)(j % 3) * STAGE_BYTES;
        #pragma unroll
        for (int kk = 0; kk < 4; kk++) {
            uint32_t b[2][4];
            #pragma unroll
            for (int p = 0; p < 2; p++) {
                const int k   = kk * 16 + r15;
                const int ncg = wn * 4 + p * 2 + hi;
                ldsm4t(b[p], st + 16384 + (uint32_t)((k * 8 + (ncg ^ s7)) * 16));
            }
            uint32_t a[2][4];
            #pragma unroll
            for (int mf = 0; mf < 2; mf++) {
                const int row = mbase + mf * 16 + r15;
                ldsm4(a[mf], st + (uint32_t)(row * 128) + (uint32_t)(((kk * 2 + hi) ^ s7) * 16));
            }
            #pragma unroll
            for (int mf = 0; mf < 2; mf++)
                #pragma unroll
                for (int nf = 0; nf < 4; nf++)
                    mma16816(acc[mf][nf], a[mf], b[nf >> 1][(nf & 1) * 2],
                             b[nf >> 1][(nf & 1) * 2 + 1]);
        }
    }

    // epilogue: bias + ReLU + float2 stores
    const int qrow = lane >> 2;
    const int qcol = (lane & 3) * 2;
    #pragma unroll
    for (int mf = 0; mf < 2; mf++) {
        const int row0 = m0 + mbase + mf * 16 + qrow;
        const float bi0 = g_biaso[row0];
        const float bi1 = g_biaso[row0 + 8];
        float* o0 = out + (size_t)row0 * HW + n0 + nbase + qcol;
        float* o1 = out + (size_t)(row0 + 8) * HW + n0 + nbase + qcol;
        #pragma unroll
        for (int nf = 0; nf < 4; nf++) {
            float2 v0, v1;
            v0.x = fmaxf(acc[mf][nf][0] + bi0, 0.f);
            v0.y = fmaxf(acc[mf][nf][1] + bi0, 0.f);
            v1.x = fmaxf(acc[mf][nf][2] + bi1, 0.f);
            v1.y = fmaxf(acc[mf][nf][3] + bi1, 0.f);
            *(float2*)(o0 + nf * 8) = v0;
            *(float2*)(o1 + nf * 8) = v1;
        }
    }
}

// ---------------- launch ----------------
extern "C" void kernel_launch(void* const* d_in, const int* in_sizes, int n_in,
                              void* d_out, int out_size) {
    const float* x        = (const float*)d_in[0];
    const float* gn_scale = (const float*)d_in[1];
    const float* gn_bias  = (const float*)d_in[2];
    const float* w_proj   = (const float*)d_in[3];
    float* out = (float*)d_out;

    cudaFuncSetAttribute(gemm_mma_kernel,
                         cudaFuncAttributeMaxDynamicSharedMemorySize, GEMM_SMEM);

    dim3 hgrid(256, 2);
    haar_kernel<<<hgrid, 256>>>(x);
    foldw_kernel<<<COUT, 256>>>(w_proj, gn_scale, gn_bias);
    dim3 grid(HW / 64, COUT / 128);
    gemm_mma_kernel<<<grid, 256, GEMM_SMEM>>>(out);
}